// round 6
// baseline (speedup 1.0000x reference)
#include <cuda_runtime.h>

// Problem constants
#define BB   4
#define CC   16
#define HH   64
#define WW   64
#define FF   32
#define K2   9

// Repacked coefficients: [f][c][k][3 float4]
//   g=0: {n0,n1,n2,n3}   g=1: {n4,n5,d0,d1}   g=2: {d2,d3,0,0}
__device__ float4 g_coefR[FF * CC * K2 * 3];   // 13824 float4 = 221 KB

__device__ __forceinline__ float rcp_fast(float q) {
    float r; asm("rcp.approx.f32 %0, %1;" : "=f"(r) : "f"(q)); return r;
}

// ---------------------------------------------------------------------------
// Kernel 1: repack coefficients into [f][c][k][g] float4
// ---------------------------------------------------------------------------
__global__ void repack_coefs_kernel(const float* __restrict__ nums,
                                    const float* __restrict__ denoms) {
    int idx = blockIdx.x * blockDim.x + threadIdx.x;
    const int total = FF * CC * K2 * 3;
    if (idx >= total) return;
    int g = idx % 3;
    int k = (idx / 3) % K2;
    int c = (idx / (3 * K2)) % CC;
    int f = idx / (3 * K2 * CC);
    const float* np = nums   + (((f * CC + c) * K2) + k) * 6;
    const float* dp = denoms + (((f * CC + c) * K2) + k) * 4;
    float4 v;
    if (g == 0)      v = make_float4(np[0], np[1], np[2], np[3]);
    else if (g == 1) v = make_float4(np[4], np[5], dp[0], dp[1]);
    else             v = make_float4(dp[2], dp[3], 0.f, 0.f);
    g_coefR[idx] = v;
}

// ---------------------------------------------------------------------------
// Kernel 2: rational (Pade) conv — lane = pixel, warp = output channel f.
//   grid  = (W/32, H, B*4) = (2, 64, 16) = 2048 blocks
//   block = 256 threads = 8 warps; warp w -> f = fgrp*8 + w
//   All 8 warps share the same 32-pixel x tile (all 16 channels).
// ---------------------------------------------------------------------------
__global__ __launch_bounds__(256)
void rational_conv_kernel(const float* __restrict__ x, float* __restrict__ out) {
    // halo tile: 16 channels x 3 rows x 34 cols (cols wbase-1 .. wbase+32)
    __shared__ float xs[CC][3][34];

    const int wbase = blockIdx.x * 32;
    const int h     = blockIdx.y;
    const int zz    = blockIdx.z;          // 0..15
    const int b     = zz >> 2;
    const int fgrp  = zz & 3;
    const int tid   = threadIdx.x;
    const int lane  = tid & 31;            // pixel within tile
    const int warp  = tid >> 5;            // 0..7
    const int f     = fgrp * 8 + warp;

    // --- Load input halo: 16 channels x 3 rows x 34 cols, zero-padded
    for (int i = tid; i < CC * 3 * 34; i += 256) {
        int j  = i % 34;
        int r  = (i / 34) % 3;
        int c  = i / 102;
        int hh = h - 1 + r;
        int ww = wbase - 1 + j;
        float v = 0.0f;
        if (hh >= 0 && hh < HH && ww >= 0 && ww < WW)
            v = x[((b * CC + c) * HH + hh) * WW + ww];
        xs[c][r][j] = v;
    }
    __syncthreads();

    const float4* __restrict__ cf = g_coefR + f * (CC * K2 * 3);
    float acc = 0.0f;

    #pragma unroll 1
    for (int c = 0; c < CC; ++c) {
        const float4* cfc = cf + c * (K2 * 3);
        #pragma unroll
        for (int a = 0; a < 3; ++a) {
            // 3 taps, stride-1 across lanes (conflict-free LDS)
            const float x0 = xs[c][a][lane];
            const float x1 = xs[c][a][lane + 1];
            const float x2 = xs[c][a][lane + 2];
            const float xv3[3] = {x0, x1, x2};
            #pragma unroll
            for (int bb = 0; bb < 3; ++bb) {
                // warp-uniform coefficient loads (L1/L2-resident, broadcast)
                const float4* cp = cfc + (a * 3 + bb) * 3;
                const float4 A = __ldg(cp);
                const float4 Bv = __ldg(cp + 1);
                const float4 Cv = __ldg(cp + 2);
                const float xv = xv3[bb];
                // P(x): Horner, 5 FMA
                float p = fmaf(xv, Bv.y, Bv.x);   // n5*x + n4
                p = fmaf(xv, p, A.w);
                p = fmaf(xv, p, A.z);
                p = fmaf(xv, p, A.y);
                p = fmaf(xv, p, A.x);
                // S(x) = x*(d0 + d1 x + d2 x^2 + d3 x^3): 3 FMA + 1 MUL
                float s = fmaf(xv, Cv.y, Cv.x);   // d3*x + d2
                s = fmaf(xv, s, Bv.w);
                s = fmaf(xv, s, Bv.z);
                s *= xv;
                const float q = 1.0f + fabsf(s);  // |s| folds into FADD
                acc = fmaf(p, rcp_fast(q), acc);
            }
        }
    }

    // --- Coalesced output store: out[b][f][h][wbase+lane]
    out[((b * FF + f) * HH + h) * WW + wbase + lane] = acc;
}

// ---------------------------------------------------------------------------
// Launch
// ---------------------------------------------------------------------------
extern "C" void kernel_launch(void* const* d_in, const int* in_sizes, int n_in,
                              void* d_out, int out_size) {
    const float* x      = (const float*)d_in[0];   // (4,16,64,64)
    const float* nums   = (const float*)d_in[1];   // (32,16,3,3,6)
    const float* denoms = (const float*)d_in[2];   // (32,16,3,3,4)
    float* out = (float*)d_out;                    // (4,32,64,64)

    const int total = FF * CC * K2 * 3;
    repack_coefs_kernel<<<(total + 255) / 256, 256>>>(nums, denoms);

    dim3 grid(WW / 32, HH, BB * 4);
    rational_conv_kernel<<<grid, 256>>>(x, out);
}

// round 7
// speedup vs baseline: 1.5890x; 1.5890x over previous
#include <cuda_runtime.h>

// Problem constants
#define BB   4
#define CC   16
#define HH   64
#define WW   64
#define FF   32
#define K2   9

#define TILE_W   16     // pixels per block
#define THREADS  64     // 2 warps; each warp: 8 px, lane = f
#define XCOLS    20     // 18 halo cols padded to 20 (80B rows, 16B aligned)

// Repacked coefficients: [c][k][g][f] float4
//   g=0: {n0,n1,n2,n3}   g=1: {n4,n5,d0,d1}   g=2: {d2,d3,0,0}
__device__ float4 g_coef4[CC * K2 * 3 * FF];   // 221 KB (L1/L2 resident)

__device__ __forceinline__ float rcp_fast(float q) {
    float r; asm("rcp.approx.f32 %0, %1;" : "=f"(r) : "f"(q)); return r;
}

// ---------------------------------------------------------------------------
// Kernel 1: repack coefficients into [c][k][g][f] float4 (dense per-warp loads)
// ---------------------------------------------------------------------------
__global__ void repack_coefs_kernel(const float* __restrict__ nums,
                                    const float* __restrict__ denoms) {
    int idx = blockIdx.x * blockDim.x + threadIdx.x;
    const int total = CC * K2 * 3 * FF;
    if (idx >= total) return;
    int f = idx & (FF - 1);
    int g = (idx >> 5) % 3;
    int k = (idx >> 5) / 3 % K2;
    int c = idx / (FF * 3 * K2);
    const float* np = nums   + (((f * CC + c) * K2) + k) * 6;
    const float* dp = denoms + (((f * CC + c) * K2) + k) * 4;
    float4 v;
    if (g == 0)      v = make_float4(np[0], np[1], np[2], np[3]);
    else if (g == 1) v = make_float4(np[4], np[5], dp[0], dp[1]);
    else             v = make_float4(dp[2], dp[3], 0.f, 0.f);
    g_coef4[idx] = v;
}

// ---------------------------------------------------------------------------
// Kernel 2: rational (Pade) conv.
//   grid  = (W/16, H, B) = (4, 64, 4) = 1024 blocks  (6.9 CTA/SM, balanced)
//   block = 64 threads = 2 warps; lane = f, warp -> 8 consecutive pixels
//   Coeffs: direct LDG.128 from repacked table (no smem staging, no syncs)
// ---------------------------------------------------------------------------
__global__ __launch_bounds__(THREADS)
void rational_conv_kernel(const float* __restrict__ x, float* __restrict__ out) {
    __shared__ __align__(16) float xs[CC][3][XCOLS];   // halo tile, 3.75 KB

    const int wbase = blockIdx.x * TILE_W;
    const int h     = blockIdx.y;
    const int b     = blockIdx.z;
    const int tid   = threadIdx.x;
    const int lane  = tid & 31;            // f
    const int warp  = tid >> 5;            // 0..1
    const int px0   = warp * 8;            // pixel offset inside tile

    // --- Load halo: 16 channels x 3 rows x 18 cols (wbase-1 .. wbase+16)
    for (int i = tid; i < CC * 3 * 18; i += THREADS) {
        int j  = i % 18;
        int r  = (i / 18) % 3;
        int c  = i / 54;
        int hh = h - 1 + r;
        int ww = wbase - 1 + j;
        float v = 0.0f;
        if (hh >= 0 && hh < HH && ww >= 0 && ww < WW)
            v = x[((b * CC + c) * HH + hh) * WW + ww];
        xs[c][r][j] = v;
    }
    __syncthreads();

    float acc[8];
    #pragma unroll
    for (int i = 0; i < 8; ++i) acc[i] = 0.0f;

    #pragma unroll 1
    for (int c = 0; c < CC; ++c) {
        const float4* __restrict__ cbase =
            g_coef4 + (c * K2) * 3 * FF + lane;
        #pragma unroll
        for (int a = 0; a < 3; ++a) {
            // 12-float register window via 3 broadcast LDS.128
            const float* xrow = &xs[c][a][px0];
            float4 xA = *reinterpret_cast<const float4*>(xrow);
            float4 xB = *reinterpret_cast<const float4*>(xrow + 4);
            float4 xC = *reinterpret_cast<const float4*>(xrow + 8);
            const float xw[12] = {xA.x, xA.y, xA.z, xA.w,
                                  xB.x, xB.y, xB.z, xB.w,
                                  xC.x, xC.y, xC.z, xC.w};
            #pragma unroll
            for (int bb = 0; bb < 3; ++bb) {
                // 3 dense LDG.128 (lane-strided 16B -> 512B/warp, 4 sectors)
                const float4* cp = cbase + ((a * 3 + bb) * 3) * FF;
                const float4 A = __ldg(cp);
                const float4 Bv = __ldg(cp + FF);
                const float4 Cv = __ldg(cp + 2 * FF);
                #pragma unroll
                for (int i = 0; i < 8; ++i) {
                    const float xv = xw[i + bb];
                    // P(x): Horner, 5 FMA
                    float p = fmaf(xv, Bv.y, Bv.x);   // n5*x + n4
                    p = fmaf(xv, p, A.w);
                    p = fmaf(xv, p, A.z);
                    p = fmaf(xv, p, A.y);
                    p = fmaf(xv, p, A.x);
                    // S(x) = x*(d0 + d1 x + d2 x^2 + d3 x^3)
                    float s = fmaf(xv, Cv.y, Cv.x);   // d3*x + d2
                    s = fmaf(xv, s, Bv.w);
                    s = fmaf(xv, s, Bv.z);
                    s *= xv;
                    const float q = 1.0f + fabsf(s);  // |s| folds into FADD
                    acc[i] = fmaf(p, rcp_fast(q), acc[i]);
                }
            }
        }
    }

    // --- Store 8 consecutive pixels per lane: 2 x STG.128
    float* op = out + ((b * FF + lane) * HH + h) * WW + wbase + px0;
    *reinterpret_cast<float4*>(op)     = make_float4(acc[0], acc[1], acc[2], acc[3]);
    *reinterpret_cast<float4*>(op + 4) = make_float4(acc[4], acc[5], acc[6], acc[7]);
}

// ---------------------------------------------------------------------------
// Launch
// ---------------------------------------------------------------------------
extern "C" void kernel_launch(void* const* d_in, const int* in_sizes, int n_in,
                              void* d_out, int out_size) {
    const float* x      = (const float*)d_in[0];   // (4,16,64,64)
    const float* nums   = (const float*)d_in[1];   // (32,16,3,3,6)
    const float* denoms = (const float*)d_in[2];   // (32,16,3,3,4)
    float* out = (float*)d_out;                    // (4,32,64,64)

    const int total = CC * K2 * 3 * FF;
    repack_coefs_kernel<<<(total + 255) / 256, 256>>>(nums, denoms);

    dim3 grid(WW / TILE_W, HH, BB);
    rational_conv_kernel<<<grid, THREADS>>>(x, out);
}

// round 8
// speedup vs baseline: 1.6112x; 1.0140x over previous
#include <cuda_runtime.h>

// Problem constants
#define BB   4
#define CC   16
#define HH   64
#define WW   64
#define FF   32
#define K2   9

#define TILE_W   16     // pixels per block
#define THREADS  64     // 2 warps; each warp: 8 px, lane = f
#define XCOLS    20     // 18 halo cols padded to 20 (80B rows, 16B aligned)

// Repacked coefficients: [c][k][g][f] float4
//   g=0: {n0,n1,n2,n3}   g=1: {n4,n5,d0,d1}   g=2: {d2,d3,0,0}
__device__ float4 g_coef4[CC * K2 * 3 * FF];   // 221 KB (L1/L2 resident)

__device__ __forceinline__ float rcp_fast(float q) {
    float r; asm("rcp.approx.f32 %0, %1;" : "=f"(r) : "f"(q)); return r;
}

// ---------------------------------------------------------------------------
// Kernel 1: repack coefficients into [c][k][g][f] float4 (dense per-warp loads)
// ---------------------------------------------------------------------------
__global__ void repack_coefs_kernel(const float* __restrict__ nums,
                                    const float* __restrict__ denoms) {
    int idx = blockIdx.x * blockDim.x + threadIdx.x;
    const int total = CC * K2 * 3 * FF;
    if (idx >= total) return;
    int f = idx & (FF - 1);
    int g = (idx >> 5) % 3;
    int k = (idx >> 5) / 3 % K2;
    int c = idx / (FF * 3 * K2);
    const float* np = nums   + (((f * CC + c) * K2) + k) * 6;
    const float* dp = denoms + (((f * CC + c) * K2) + k) * 4;
    float4 v;
    if (g == 0)      v = make_float4(np[0], np[1], np[2], np[3]);
    else if (g == 1) v = make_float4(np[4], np[5], dp[0], dp[1]);
    else             v = make_float4(dp[2], dp[3], 0.f, 0.f);
    g_coef4[idx] = v;
}

// ---------------------------------------------------------------------------
// Kernel 2: rational (Pade) conv.
//   grid  = (W/16, H, B) = (4, 64, 4) = 1024 blocks  (6.9 CTA/SM, balanced)
//   block = 64 threads = 2 warps; lane = f, warp -> 8 consecutive pixels
//   Coeffs: direct LDG.128 from repacked table (no smem staging, no syncs)
// ---------------------------------------------------------------------------
__global__ __launch_bounds__(THREADS)
void rational_conv_kernel(const float* __restrict__ x, float* __restrict__ out) {
    __shared__ __align__(16) float xs[CC][3][XCOLS];   // halo tile, 3.75 KB

    const int wbase = blockIdx.x * TILE_W;
    const int h     = blockIdx.y;
    const int b     = blockIdx.z;
    const int tid   = threadIdx.x;
    const int lane  = tid & 31;            // f
    const int warp  = tid >> 5;            // 0..1
    const int px0   = warp * 8;            // pixel offset inside tile

    // --- Load halo: 16 channels x 3 rows x 18 cols (wbase-1 .. wbase+16)
    for (int i = tid; i < CC * 3 * 18; i += THREADS) {
        int j  = i % 18;
        int r  = (i / 18) % 3;
        int c  = i / 54;
        int hh = h - 1 + r;
        int ww = wbase - 1 + j;
        float v = 0.0f;
        if (hh >= 0 && hh < HH && ww >= 0 && ww < WW)
            v = x[((b * CC + c) * HH + hh) * WW + ww];
        xs[c][r][j] = v;
    }
    __syncthreads();

    float acc[8];
    #pragma unroll
    for (int i = 0; i < 8; ++i) acc[i] = 0.0f;

    #pragma unroll 1
    for (int c = 0; c < CC; ++c) {
        const float4* __restrict__ cbase =
            g_coef4 + (c * K2) * 3 * FF + lane;
        #pragma unroll
        for (int a = 0; a < 3; ++a) {
            // 12-float register window via 3 broadcast LDS.128
            const float* xrow = &xs[c][a][px0];
            float4 xA = *reinterpret_cast<const float4*>(xrow);
            float4 xB = *reinterpret_cast<const float4*>(xrow + 4);
            float4 xC = *reinterpret_cast<const float4*>(xrow + 8);
            const float xw[12] = {xA.x, xA.y, xA.z, xA.w,
                                  xB.x, xB.y, xB.z, xB.w,
                                  xC.x, xC.y, xC.z, xC.w};
            #pragma unroll
            for (int bb = 0; bb < 3; ++bb) {
                // 3 dense LDG.128 (lane-strided 16B -> 512B/warp, 4 sectors)
                const float4* cp = cbase + ((a * 3 + bb) * 3) * FF;
                const float4 A = __ldg(cp);
                const float4 Bv = __ldg(cp + FF);
                const float4 Cv = __ldg(cp + 2 * FF);
                #pragma unroll
                for (int i = 0; i < 8; ++i) {
                    const float xv = xw[i + bb];
                    // P(x): Horner, 5 FMA
                    float p = fmaf(xv, Bv.y, Bv.x);   // n5*x + n4
                    p = fmaf(xv, p, A.w);
                    p = fmaf(xv, p, A.z);
                    p = fmaf(xv, p, A.y);
                    p = fmaf(xv, p, A.x);
                    // S(x) = x*(d0 + d1 x + d2 x^2 + d3 x^3)
                    float s = fmaf(xv, Cv.y, Cv.x);   // d3*x + d2
                    s = fmaf(xv, s, Bv.w);
                    s = fmaf(xv, s, Bv.z);
                    s *= xv;
                    const float q = 1.0f + fabsf(s);  // |s| folds into FADD
                    acc[i] = fmaf(p, rcp_fast(q), acc[i]);
                }
            }
        }
    }

    // --- Store 8 consecutive pixels per lane: 2 x STG.128
    float* op = out + ((b * FF + lane) * HH + h) * WW + wbase + px0;
    *reinterpret_cast<float4*>(op)     = make_float4(acc[0], acc[1], acc[2], acc[3]);
    *reinterpret_cast<float4*>(op + 4) = make_float4(acc[4], acc[5], acc[6], acc[7]);
}

// ---------------------------------------------------------------------------
// Launch
// ---------------------------------------------------------------------------
extern "C" void kernel_launch(void* const* d_in, const int* in_sizes, int n_in,
                              void* d_out, int out_size) {
    const float* x      = (const float*)d_in[0];   // (4,16,64,64)
    const float* nums   = (const float*)d_in[1];   // (32,16,3,3,6)
    const float* denoms = (const float*)d_in[2];   // (32,16,3,3,4)
    float* out = (float*)d_out;                    // (4,32,64,64)

    const int total = CC * K2 * 3 * FF;
    repack_coefs_kernel<<<(total + 255) / 256, 256>>>(nums, denoms);

    dim3 grid(WW / TILE_W, HH, BB);
    rational_conv_kernel<<<grid, THREADS>>>(x, out);
}

// round 9
// speedup vs baseline: 1.6214x; 1.0063x over previous
#include <cuda_runtime.h>

// Problem constants
#define BB   4
#define CC   16
#define HH   64
#define WW   64
#define FF   32
#define K2   9

#define TILE_W   16     // pixels per block
#define THREADS  64     // 2 warps; each warp: 8 px, lane = f
#define XCOLS    20     // 18 halo cols padded to 20 (80B rows, 16B aligned)

// Repacked coefficients: [c][k][g][f] float4
//   g=0: {n0,n1,n2,n3}   g=1: {n4,n5,d0,d1}   g=2: {d2,d3,0,0}
__device__ float4 g_coef4[CC * K2 * 3 * FF];   // 221 KB (L1/L2 resident)

__device__ __forceinline__ float rcp_fast(float q) {
    float r; asm("rcp.approx.f32 %0, %1;" : "=f"(r) : "f"(q)); return r;
}

// ---------------------------------------------------------------------------
// Kernel 1: repack coefficients into [c][k][g][f] float4 (dense per-warp loads)
// ---------------------------------------------------------------------------
__global__ void repack_coefs_kernel(const float* __restrict__ nums,
                                    const float* __restrict__ denoms) {
    int idx = blockIdx.x * blockDim.x + threadIdx.x;
    const int total = CC * K2 * 3 * FF;
    if (idx >= total) return;
    int f = idx & (FF - 1);
    int g = (idx >> 5) % 3;
    int k = (idx >> 5) / 3 % K2;
    int c = idx / (FF * 3 * K2);
    const float* np = nums   + (((f * CC + c) * K2) + k) * 6;
    const float* dp = denoms + (((f * CC + c) * K2) + k) * 4;
    float4 v;
    if (g == 0)      v = make_float4(np[0], np[1], np[2], np[3]);
    else if (g == 1) v = make_float4(np[4], np[5], dp[0], dp[1]);
    else             v = make_float4(dp[2], dp[3], 0.f, 0.f);
    g_coef4[idx] = v;
}

// ---------------------------------------------------------------------------
// Kernel 2: rational (Pade) conv.
//   grid  = (W/16, H, B) = (4, 64, 4) = 1024 blocks  (6.9 CTA/SM, balanced)
//   block = 64 threads = 2 warps; lane = f, warp -> 8 consecutive pixels
//   Coeffs: direct LDG.128 from repacked table (no smem staging, no syncs)
// ---------------------------------------------------------------------------
__global__ __launch_bounds__(THREADS)
void rational_conv_kernel(const float* __restrict__ x, float* __restrict__ out) {
    __shared__ __align__(16) float xs[CC][3][XCOLS];   // halo tile, 3.75 KB

    const int wbase = blockIdx.x * TILE_W;
    const int h     = blockIdx.y;
    const int b     = blockIdx.z;
    const int tid   = threadIdx.x;
    const int lane  = tid & 31;            // f
    const int warp  = tid >> 5;            // 0..1
    const int px0   = warp * 8;            // pixel offset inside tile

    // --- Load halo: 16 channels x 3 rows x 18 cols (wbase-1 .. wbase+16)
    for (int i = tid; i < CC * 3 * 18; i += THREADS) {
        int j  = i % 18;
        int r  = (i / 18) % 3;
        int c  = i / 54;
        int hh = h - 1 + r;
        int ww = wbase - 1 + j;
        float v = 0.0f;
        if (hh >= 0 && hh < HH && ww >= 0 && ww < WW)
            v = x[((b * CC + c) * HH + hh) * WW + ww];
        xs[c][r][j] = v;
    }
    __syncthreads();

    float acc[8];
    #pragma unroll
    for (int i = 0; i < 8; ++i) acc[i] = 0.0f;

    #pragma unroll 1
    for (int c = 0; c < CC; ++c) {
        const float4* __restrict__ cbase =
            g_coef4 + (c * K2) * 3 * FF + lane;
        #pragma unroll
        for (int a = 0; a < 3; ++a) {
            // 12-float register window via 3 broadcast LDS.128
            const float* xrow = &xs[c][a][px0];
            float4 xA = *reinterpret_cast<const float4*>(xrow);
            float4 xB = *reinterpret_cast<const float4*>(xrow + 4);
            float4 xC = *reinterpret_cast<const float4*>(xrow + 8);
            const float xw[12] = {xA.x, xA.y, xA.z, xA.w,
                                  xB.x, xB.y, xB.z, xB.w,
                                  xC.x, xC.y, xC.z, xC.w};
            #pragma unroll
            for (int bb = 0; bb < 3; ++bb) {
                // 3 dense LDG.128 (lane-strided 16B -> 512B/warp, 4 sectors)
                const float4* cp = cbase + ((a * 3 + bb) * 3) * FF;
                const float4 A = __ldg(cp);
                const float4 Bv = __ldg(cp + FF);
                const float4 Cv = __ldg(cp + 2 * FF);
                #pragma unroll
                for (int i = 0; i < 8; ++i) {
                    const float xv = xw[i + bb];
                    // P(x): Horner, 5 FMA
                    float p = fmaf(xv, Bv.y, Bv.x);   // n5*x + n4
                    p = fmaf(xv, p, A.w);
                    p = fmaf(xv, p, A.z);
                    p = fmaf(xv, p, A.y);
                    p = fmaf(xv, p, A.x);
                    // S(x) = x*(d0 + d1 x + d2 x^2 + d3 x^3)
                    float s = fmaf(xv, Cv.y, Cv.x);   // d3*x + d2
                    s = fmaf(xv, s, Bv.w);
                    s = fmaf(xv, s, Bv.z);
                    s *= xv;
                    const float q = 1.0f + fabsf(s);  // |s| folds into FADD
                    acc[i] = fmaf(p, rcp_fast(q), acc[i]);
                }
            }
        }
    }

    // --- Store 8 consecutive pixels per lane: 2 x STG.128
    float* op = out + ((b * FF + lane) * HH + h) * WW + wbase + px0;
    *reinterpret_cast<float4*>(op)     = make_float4(acc[0], acc[1], acc[2], acc[3]);
    *reinterpret_cast<float4*>(op + 4) = make_float4(acc[4], acc[5], acc[6], acc[7]);
}

// ---------------------------------------------------------------------------
// Launch
// ---------------------------------------------------------------------------
extern "C" void kernel_launch(void* const* d_in, const int* in_sizes, int n_in,
                              void* d_out, int out_size) {
    const float* x      = (const float*)d_in[0];   // (4,16,64,64)
    const float* nums   = (const float*)d_in[1];   // (32,16,3,3,6)
    const float* denoms = (const float*)d_in[2];   // (32,16,3,3,4)
    float* out = (float*)d_out;                    // (4,32,64,64)

    const int total = CC * K2 * 3 * FF;
    repack_coefs_kernel<<<(total + 255) / 256, 256>>>(nums, denoms);

    dim3 grid(WW / TILE_W, HH, BB);
    rational_conv_kernel<<<grid, THREADS>>>(x, out);
}

// round 10
// speedup vs baseline: 2.0810x; 1.2835x over previous
#include <cuda_runtime.h>

// Problem constants
#define BB   4
#define CC   16
#define HH   64
#define WW   64
#define FF   32
#define K2   9

#define TILE_W   16     // pixels per block
#define THREADS  128    // 4 warps: (c-half 0: px 0-7, 8-15), (c-half 1: px 0-7, 8-15)
#define XCOLS    20     // 18 halo cols padded to 20 (80B rows, 16B aligned)

// Repacked coefficients: [c][k][g][f] float4
//   g=0: {n0,n1,n2,n3}   g=1: {n4,n5,d0,d1}   g=2: {d2,d3,0,0}
__device__ float4 g_coef4[CC * K2 * 3 * FF];   // 221 KB (L2 resident)

__device__ __forceinline__ float rcp_fast(float q) {
    float r; asm("rcp.approx.f32 %0, %1;" : "=f"(r) : "f"(q)); return r;
}

// ---------------------------------------------------------------------------
// Kernel 1: repack coefficients into [c][k][g][f] float4
// ---------------------------------------------------------------------------
__global__ void repack_coefs_kernel(const float* __restrict__ nums,
                                    const float* __restrict__ denoms) {
    int idx = blockIdx.x * blockDim.x + threadIdx.x;
    const int total = CC * K2 * 3 * FF;
    if (idx >= total) return;
    int f = idx & (FF - 1);
    int g = (idx >> 5) % 3;
    int k = (idx >> 5) / 3 % K2;
    int c = idx / (FF * 3 * K2);
    const float* np = nums   + (((f * CC + c) * K2) + k) * 6;
    const float* dp = denoms + (((f * CC + c) * K2) + k) * 4;
    float4 v;
    if (g == 0)      v = make_float4(np[0], np[1], np[2], np[3]);
    else if (g == 1) v = make_float4(np[4], np[5], dp[0], dp[1]);
    else             v = make_float4(dp[2], dp[3], 0.f, 0.f);
    g_coef4[idx] = v;
}

// ---------------------------------------------------------------------------
// Kernel 2: rational (Pade) conv.
//   grid  = (W/16, H, B) = (4, 64, 4) = 1024 blocks, 128 threads (4 warps)
//   lane = f. warp = {c-half, px-half}: warps 0/1 -> channels 0-7,
//   warps 2/3 -> channels 8-15; px0 = (warp&1)*8.
//   Coefficients: direct LDG.128, register double-buffered across k.
//   Partial sums over c-halves combined via smem reduction.
// ---------------------------------------------------------------------------
__global__ __launch_bounds__(THREADS, 7)
void rational_conv_kernel(const float* __restrict__ x, float* __restrict__ out) {
    __shared__ __align__(16) float xs[CC][3][XCOLS];   // 3.75 KB
    __shared__ float red[2][32][9];                    // partial sums, pad 9

    const int wbase = blockIdx.x * TILE_W;
    const int h     = blockIdx.y;
    const int b     = blockIdx.z;
    const int tid   = threadIdx.x;
    const int lane  = tid & 31;            // f
    const int warp  = tid >> 5;            // 0..3
    const int chalf = warp >> 1;           // 0..1
    const int pxw   = warp & 1;            // 0..1
    const int px0   = pxw * 8;

    // --- Load halo: 16 channels x 3 rows x 18 cols (wbase-1 .. wbase+16)
    for (int i = tid; i < CC * 3 * 18; i += THREADS) {
        int j  = i % 18;
        int r  = (i / 18) % 3;
        int c  = i / 54;
        int hh = h - 1 + r;
        int ww = wbase - 1 + j;
        float v = 0.0f;
        if (hh >= 0 && hh < HH && ww >= 0 && ww < WW)
            v = x[((b * CC + c) * HH + hh) * WW + ww];
        xs[c][r][j] = v;
    }
    __syncthreads();

    float acc[8];
    #pragma unroll
    for (int i = 0; i < 8; ++i) acc[i] = 0.0f;

    const int cstart = chalf * 8;
    const float4* __restrict__ cbase =
        g_coef4 + (cstart * K2) * 3 * FF + lane;

    // prime the coefficient pipeline: (c=cstart, k=0)
    float4 A  = __ldg(cbase);
    float4 Bv = __ldg(cbase + FF);
    float4 Cv = __ldg(cbase + 2 * FF);

    #pragma unroll 1
    for (int cc = 0; cc < 8; ++cc) {
        const float4* cfc = cbase + cc * (K2 * 3 * FF);
        #pragma unroll
        for (int a = 0; a < 3; ++a) {
            // 12-float register window via 3 broadcast LDS.128
            const float* xrow = &xs[cstart + cc][a][px0];
            float4 xA = *reinterpret_cast<const float4*>(xrow);
            float4 xB = *reinterpret_cast<const float4*>(xrow + 4);
            float4 xC = *reinterpret_cast<const float4*>(xrow + 8);
            const float xw[12] = {xA.x, xA.y, xA.z, xA.w,
                                  xB.x, xB.y, xB.z, xB.w,
                                  xC.x, xC.y, xC.z, xC.w};
            #pragma unroll
            for (int bb = 0; bb < 3; ++bb) {
                const int k = a * 3 + bb;
                // --- prefetch next (c,k) coeffs while computing current
                const float4* np;
                if (k < 8)        np = cfc + (k + 1) * 3 * FF;
                else if (cc < 7)  np = cfc + K2 * 3 * FF;       // next c, k=0
                else              np = cfc + k * 3 * FF;        // dummy (last)
                float4 An  = __ldg(np);
                float4 Bn  = __ldg(np + FF);
                float4 Cn  = __ldg(np + 2 * FF);

                const float n0 = A.x,  n1 = A.y,  n2 = A.z,  n3 = A.w;
                const float n4 = Bv.x, n5 = Bv.y, d0 = Bv.z, d1 = Bv.w;
                const float d2 = Cv.x, d3 = Cv.y;
                #pragma unroll
                for (int i = 0; i < 8; ++i) {
                    const float xv = xw[i + bb];
                    // P(x): Horner, 5 FMA
                    float p = fmaf(xv, n5, n4);
                    p = fmaf(xv, p, n3);
                    p = fmaf(xv, p, n2);
                    p = fmaf(xv, p, n1);
                    p = fmaf(xv, p, n0);
                    // S(x) = x*(d0 + d1 x + d2 x^2 + d3 x^3)
                    float s = fmaf(xv, d3, d2);
                    s = fmaf(xv, s, d1);
                    s = fmaf(xv, s, d0);
                    s *= xv;
                    const float q = 1.0f + fabsf(s);   // |s| folds into FADD
                    acc[i] = fmaf(p, rcp_fast(q), acc[i]);
                }
                A = An; Bv = Bn; Cv = Cn;
            }
        }
    }

    // --- Combine the two c-halves via smem (deterministic 2-way add)
    if (chalf == 1) {
        #pragma unroll
        for (int i = 0; i < 8; ++i) red[pxw][lane][i] = acc[i];
    }
    __syncthreads();
    if (chalf == 0) {
        #pragma unroll
        for (int i = 0; i < 8; ++i) acc[i] += red[pxw][lane][i];
        float* op = out + ((b * FF + lane) * HH + h) * WW + wbase + px0;
        *reinterpret_cast<float4*>(op)     = make_float4(acc[0], acc[1], acc[2], acc[3]);
        *reinterpret_cast<float4*>(op + 4) = make_float4(acc[4], acc[5], acc[6], acc[7]);
    }
}

// ---------------------------------------------------------------------------
// Launch
// ---------------------------------------------------------------------------
extern "C" void kernel_launch(void* const* d_in, const int* in_sizes, int n_in,
                              void* d_out, int out_size) {
    const float* x      = (const float*)d_in[0];   // (4,16,64,64)
    const float* nums   = (const float*)d_in[1];   // (32,16,3,3,6)
    const float* denoms = (const float*)d_in[2];   // (32,16,3,3,4)
    float* out = (float*)d_out;                    // (4,32,64,64)

    const int total = CC * K2 * 3 * FF;
    repack_coefs_kernel<<<(total + 255) / 256, 256>>>(nums, denoms);

    dim3 grid(WW / TILE_W, HH, BB);
    rational_conv_kernel<<<grid, THREADS>>>(x, out);
}